// round 1
// baseline (speedup 1.0000x reference)
#include <cuda_runtime.h>

// Reference reduces EXACTLY to: out = elu(input @ W).
//   mask = eye(N)  =>  softmax(where(eye>0, e, -9e15)) == Identity (off-diag
//   exp underflows to 0.0 in fp32), so h_prime = h, out = elu(input @ W).
// adj (d_in[1]) and a (d_in[3]) are dead.
//
// GEMM: M=8192, K=2048, N=2048, fp32 in/out, fused elu epilogue.
// Baseline: 128x128 block tile, BK=16, 8x8 per thread, 256 threads/CTA.

#define GEMM_M 8192
#define GEMM_N 2048
#define GEMM_K 2048

#define BM 128
#define BN 128
#define BK 16
#define TM 8
#define TN 8
#define NTHREADS 256

__device__ __forceinline__ float elu_f(float x) {
    return x > 0.0f ? x : expm1f(x);
}

__global__ __launch_bounds__(NTHREADS, 1)
void gat_gemm_elu_kernel(const float* __restrict__ A,   // [M, K] row-major
                         const float* __restrict__ B,   // [K, N] row-major
                         float* __restrict__ C)         // [M, N] row-major
{
    __shared__ float As[BK][BM];   // A tile stored transposed: As[k][m]
    __shared__ float Bs[BK][BN];   // B tile: Bs[k][n]

    const int tid       = threadIdx.x;
    const int block_row = blockIdx.y;   // M tile index
    const int block_col = blockIdx.x;   // N tile index

    const float* A0 = A + (size_t)block_row * BM * GEMM_K;
    const float* B0 = B + (size_t)block_col * BN;
    float*       C0 = C + (size_t)block_row * BM * GEMM_N + (size_t)block_col * BN;

    // thread -> 8x8 micro-tile
    const int tRow = tid / (BN / TN);   // 0..15
    const int tCol = tid % (BN / TN);   // 0..15

    float acc[TM][TN];
    #pragma unroll
    for (int i = 0; i < TM; i++)
        #pragma unroll
        for (int j = 0; j < TN; j++)
            acc[i][j] = 0.0f;

    float ra[TM];
    float rb[TN];

    for (int kt = 0; kt < GEMM_K; kt += BK) {
        // --- load A tile (BM x BK), transposed into As[k][m], float4 GMEM reads ---
        // 128 rows x 16 cols = 512 float4; 256 threads x 2 iters
        #pragma unroll
        for (int it = 0; it < 2; it++) {
            int lin = tid + it * NTHREADS;      // 0..511
            int r   = lin >> 2;                 // 0..127 (m within tile)
            int c4  = (lin & 3) * 4;            // 0,4,8,12 (k within tile)
            float4 v = *reinterpret_cast<const float4*>(
                A0 + (size_t)r * GEMM_K + kt + c4);
            As[c4 + 0][r] = v.x;
            As[c4 + 1][r] = v.y;
            As[c4 + 2][r] = v.z;
            As[c4 + 3][r] = v.w;
        }
        // --- load B tile (BK x BN), float4 GMEM reads, direct layout ---
        // 16 rows x 128 cols = 512 float4; 256 threads x 2 iters
        #pragma unroll
        for (int it = 0; it < 2; it++) {
            int lin = tid + it * NTHREADS;      // 0..511
            int r   = lin >> 5;                 // 0..15 (k within tile)
            int c4  = (lin & 31) * 4;           // 0..124 (n within tile)
            *reinterpret_cast<float4*>(&Bs[r][c4]) =
                *reinterpret_cast<const float4*>(
                    B0 + (size_t)(kt + r) * GEMM_N + c4);
        }
        __syncthreads();

        // --- compute ---
        #pragma unroll
        for (int k = 0; k < BK; k++) {
            #pragma unroll
            for (int i = 0; i < TM; i++) ra[i] = As[k][tRow * TM + i];
            #pragma unroll
            for (int j = 0; j < TN; j++) rb[j] = Bs[k][tCol * TN + j];
            #pragma unroll
            for (int i = 0; i < TM; i++)
                #pragma unroll
                for (int j = 0; j < TN; j++)
                    acc[i][j] = fmaf(ra[i], rb[j], acc[i][j]);
        }
        __syncthreads();
    }

    // --- epilogue: fused elu, float4 stores ---
    #pragma unroll
    for (int i = 0; i < TM; i++) {
        int row = tRow * TM + i;
        #pragma unroll
        for (int j = 0; j < TN; j += 4) {
            int col = tCol * TN + j;
            float4 v;
            v.x = elu_f(acc[i][j + 0]);
            v.y = elu_f(acc[i][j + 1]);
            v.z = elu_f(acc[i][j + 2]);
            v.w = elu_f(acc[i][j + 3]);
            *reinterpret_cast<float4*>(C0 + (size_t)row * GEMM_N + col) = v;
        }
    }
}

extern "C" void kernel_launch(void* const* d_in, const int* in_sizes, int n_in,
                              void* d_out, int out_size) {
    // metadata order: input [8192,2048], adj [8192,8192] (UNUSED),
    //                 W [2048,2048], a [4096,1] (UNUSED)
    const float* input = (const float*)d_in[0];
    const float* W     = (const float*)d_in[2];
    float*       out   = (float*)d_out;

    dim3 grid(GEMM_N / BN, GEMM_M / BM);   // (16, 64)
    dim3 block(NTHREADS);
    gat_gemm_elu_kernel<<<grid, block>>>(input, W, out);
}

// round 3
// speedup vs baseline: 2.7266x; 2.7266x over previous
#include <cuda_runtime.h>
#include <cuda_bf16.h>
#include <cstdint>

// out = elu(input @ W)  [reference's softmax(eye-mask) == Identity exactly]
// fp32 GEMM M=8192 N=2048 K=2048 via bf16 3-term split on legacy tensor cores
// (mma.sync.m16n8k16 — base ISA, compiles for compute_103; tcgen05 is
// sm_103a-specific PTX which this harness's nvcc target rejects):
//   A@B = Ahi@Bhi + Ahi@Blo + Alo@Bhi    (lo*lo ~2^-18, dropped)
// Pre-pass: A -> (Ahi,Alo) bf16 [M,K]; W -> transposed (Bhi,Blo) bf16 [N,K].
// Main: 128x256 CTA tile, BK=64, 16 warps (warp tile 64x32), 2-stage cp.async.

#define GM 8192
#define GN 2048
#define GK 2048

#define BM 128
#define BN 256
#define BK 64
#define NTHREADS 512
#define NCHUNK (GK / BK)   // 32

// ---------------- scratch (bf16 split operands) ----------------
__device__ __nv_bfloat16 g_Ahi[(size_t)GM * GK];
__device__ __nv_bfloat16 g_Alo[(size_t)GM * GK];
__device__ __nv_bfloat16 g_Bhi[(size_t)GN * GK];   // W^T, K-major rows
__device__ __nv_bfloat16 g_Blo[(size_t)GN * GK];

// ---------------- smem stage layout ----------------
// per stage: Ahi 16K | Alo 16K | Bhi 32K | Blo 32K   (rows of 128B, SW128)
#define SA_HI 0
#define SA_LO 16384
#define SB_HI 32768
#define SB_LO 65536
#define STAGE_BYTES 98304
#define SMEM_TOTAL (2 * STAGE_BYTES)   // 196608

#define SWZ(o) ((o) ^ (((o) >> 3) & 0x70))

__device__ __forceinline__ uint32_t smem_u32(const void* p) {
    uint32_t a;
    asm("{ .reg .u64 t; cvta.to.shared.u64 t, %1; cvt.u32.u64 %0, t; }" : "=r"(a) : "l"(p));
    return a;
}
__device__ __forceinline__ void cp16(uint32_t dst, const void* src) {
    asm volatile("cp.async.cg.shared.global [%0], [%1], 16;" :: "r"(dst), "l"(src));
}
__device__ __forceinline__ void cp_commit() {
    asm volatile("cp.async.commit_group;" ::: "memory");
}
__device__ __forceinline__ void cp_wait1() {
    asm volatile("cp.async.wait_group 1;" ::: "memory");
}
__device__ __forceinline__ void ldsm4(uint32_t addr, uint32_t& r0, uint32_t& r1,
                                      uint32_t& r2, uint32_t& r3) {
    asm volatile("ldmatrix.sync.aligned.m8n8.x4.shared.b16 {%0,%1,%2,%3}, [%4];"
                 : "=r"(r0), "=r"(r1), "=r"(r2), "=r"(r3) : "r"(addr));
}
__device__ __forceinline__ void mma16816(float& d0, float& d1, float& d2, float& d3,
                                         uint32_t a0, uint32_t a1, uint32_t a2, uint32_t a3,
                                         uint32_t b0, uint32_t b1) {
    asm volatile(
        "mma.sync.aligned.m16n8k16.row.col.f32.bf16.bf16.f32 "
        "{%0,%1,%2,%3}, {%4,%5,%6,%7}, {%8,%9}, {%0,%1,%2,%3};"
        : "+f"(d0), "+f"(d1), "+f"(d2), "+f"(d3)
        : "r"(a0), "r"(a1), "r"(a2), "r"(a3), "r"(b0), "r"(b1));
}
__device__ __forceinline__ float elu_f(float x) { return x > 0.0f ? x : expm1f(x); }

// ---------------- conversion kernels ----------------
__global__ __launch_bounds__(256) void conv_a_kernel(const float4* __restrict__ A) {
    size_t i = (size_t)blockIdx.x * 256 + threadIdx.x;
    float4 v = A[i];
    __nv_bfloat16 h0 = __float2bfloat16(v.x), h1 = __float2bfloat16(v.y);
    __nv_bfloat16 h2 = __float2bfloat16(v.z), h3 = __float2bfloat16(v.w);
    __nv_bfloat16 l0 = __float2bfloat16(v.x - __bfloat162float(h0));
    __nv_bfloat16 l1 = __float2bfloat16(v.y - __bfloat162float(h1));
    __nv_bfloat16 l2 = __float2bfloat16(v.z - __bfloat162float(h2));
    __nv_bfloat16 l3 = __float2bfloat16(v.w - __bfloat162float(h3));
    __nv_bfloat162* ph = reinterpret_cast<__nv_bfloat162*>(g_Ahi + i * 4);
    __nv_bfloat162* pl = reinterpret_cast<__nv_bfloat162*>(g_Alo + i * 4);
    ph[0] = __nv_bfloat162(h0, h1);
    ph[1] = __nv_bfloat162(h2, h3);
    pl[0] = __nv_bfloat162(l0, l1);
    pl[1] = __nv_bfloat162(l2, l3);
}

__global__ __launch_bounds__(256) void conv_bt_kernel(const float* __restrict__ B) {
    __shared__ float tile[32][33];
    int n0 = blockIdx.x * 32, k0 = blockIdx.y * 32;
    int tx = threadIdx.x, ty = threadIdx.y;   // block (32,8)
    #pragma unroll
    for (int j = 0; j < 32; j += 8)
        tile[ty + j][tx] = B[(size_t)(k0 + ty + j) * GN + n0 + tx];
    __syncthreads();
    #pragma unroll
    for (int j = 0; j < 32; j += 8) {
        float x = tile[tx][ty + j];
        __nv_bfloat16 h = __float2bfloat16(x);
        __nv_bfloat16 l = __float2bfloat16(x - __bfloat162float(h));
        size_t o = (size_t)(n0 + ty + j) * GK + k0 + tx;
        g_Bhi[o] = h;
        g_Blo[o] = l;
    }
}

// ---------------- stage fill ----------------
__device__ __forceinline__ void fill_stage(uint32_t sbase, int m0, int n0, int k0) {
    const int tid = threadIdx.x;
    const char* Ah = (const char*)g_Ahi;
    const char* Al = (const char*)g_Alo;
    const char* Bh = (const char*)g_Bhi;
    const char* Bl = (const char*)g_Blo;
    // A tile: 128 rows x 128B (64 bf16)
    #pragma unroll
    for (int i = tid; i < 1024; i += NTHREADS) {
        int r = i >> 3, c = i & 7;
        uint32_t off = SWZ((uint32_t)(r * 128 + c * 16));
        size_t go = ((size_t)(m0 + r) * GK + k0) * 2 + c * 16;
        cp16(sbase + SA_HI + off, Ah + go);
        cp16(sbase + SA_LO + off, Al + go);
    }
    // B tile: 256 rows x 128B
    #pragma unroll
    for (int i = tid; i < 2048; i += NTHREADS) {
        int r = i >> 3, c = i & 7;
        uint32_t off = SWZ((uint32_t)(r * 128 + c * 16));
        size_t go = ((size_t)(n0 + r) * GK + k0) * 2 + c * 16;
        cp16(sbase + SB_HI + off, Bh + go);
        cp16(sbase + SB_LO + off, Bl + go);
    }
}

// ---------------- main GEMM kernel ----------------
__global__ __launch_bounds__(NTHREADS, 1)
void gat_mma_kernel(float* __restrict__ C) {
    extern __shared__ char smem[];
    uint32_t sb = smem_u32(smem);
    const int tid  = threadIdx.x;
    const int wid  = tid >> 5;
    const int lane = tid & 31;
    const int m0 = blockIdx.y * BM;
    const int n0 = blockIdx.x * BN;
    const int warp_m = wid & 1;    // 2 M-tiles of 64
    const int warp_n = wid >> 1;   // 8 N-tiles of 32

    float acc[4][4][4];
    #pragma unroll
    for (int i = 0; i < 4; i++)
        #pragma unroll
        for (int j = 0; j < 4; j++)
            #pragma unroll
            for (int t = 0; t < 4; t++) acc[i][j][t] = 0.0f;

    // per-lane ldmatrix address components
    const int a_row = lane & 15;             // row within 16-row A tile
    const int a_kb  = (lane >> 4) * 16;      // k-half byte offset
    const int b_j   = lane >> 3;             // which 8x8 matrix
    const int b_row = (lane & 7) + ((b_j >> 1) * 8);   // n row within 16-n pair
    const int b_kb  = (b_j & 1) * 16;        // k-half byte offset

    // prologue
    fill_stage(sb, m0, n0, 0);
    cp_commit();
    fill_stage(sb + STAGE_BYTES, m0, n0, BK);
    cp_commit();

    for (int k = 0; k < NCHUNK; k++) {
        uint32_t stage = sb + (uint32_t)(k & 1) * STAGE_BYTES;
        cp_wait1();
        __syncthreads();

        #pragma unroll
        for (int ks = 0; ks < 4; ks++) {
            const int kbyte = ks * 32;
            // ---- load A_hi fragments (4 m-tiles) ----
            uint32_t ah[4][4];
            #pragma unroll
            for (int mt = 0; mt < 4; mt++) {
                int row = warp_m * 64 + mt * 16 + a_row;
                uint32_t off = SWZ((uint32_t)(row * 128 + kbyte + a_kb));
                ldsm4(stage + SA_HI + off, ah[mt][0], ah[mt][1], ah[mt][2], ah[mt][3]);
            }
            // ---- load B_hi fragments (4 n-tiles via 2 x4) ----
            uint32_t bh[4][2];
            #pragma unroll
            for (int np = 0; np < 2; np++) {
                int nrow = warp_n * 32 + np * 16 + b_row;
                uint32_t off = SWZ((uint32_t)(nrow * 128 + kbyte + b_kb));
                uint32_t r0, r1, r2, r3;
                ldsm4(stage + SB_HI + off, r0, r1, r2, r3);
                bh[np * 2 + 0][0] = r0; bh[np * 2 + 0][1] = r1;
                bh[np * 2 + 1][0] = r2; bh[np * 2 + 1][1] = r3;
            }
            // ---- hi x hi ----
            #pragma unroll
            for (int mt = 0; mt < 4; mt++)
                #pragma unroll
                for (int nt = 0; nt < 4; nt++)
                    mma16816(acc[mt][nt][0], acc[mt][nt][1], acc[mt][nt][2], acc[mt][nt][3],
                             ah[mt][0], ah[mt][1], ah[mt][2], ah[mt][3],
                             bh[nt][0], bh[nt][1]);
            // ---- load B_lo, hi x lo ----
            {
                uint32_t bl[4][2];
                #pragma unroll
                for (int np = 0; np < 2; np++) {
                    int nrow = warp_n * 32 + np * 16 + b_row;
                    uint32_t off = SWZ((uint32_t)(nrow * 128 + kbyte + b_kb));
                    uint32_t r0, r1, r2, r3;
                    ldsm4(stage + SB_LO + off, r0, r1, r2, r3);
                    bl[np * 2 + 0][0] = r0; bl[np * 2 + 0][1] = r1;
                    bl[np * 2 + 1][0] = r2; bl[np * 2 + 1][1] = r3;
                }
                #pragma unroll
                for (int mt = 0; mt < 4; mt++)
                    #pragma unroll
                    for (int nt = 0; nt < 4; nt++)
                        mma16816(acc[mt][nt][0], acc[mt][nt][1], acc[mt][nt][2], acc[mt][nt][3],
                                 ah[mt][0], ah[mt][1], ah[mt][2], ah[mt][3],
                                 bl[nt][0], bl[nt][1]);
            }
            // ---- load A_lo, lo x hi ----
            {
                uint32_t al[4];
                #pragma unroll
                for (int mt = 0; mt < 4; mt++) {
                    int row = warp_m * 64 + mt * 16 + a_row;
                    uint32_t off = SWZ((uint32_t)(row * 128 + kbyte + a_kb));
                    ldsm4(stage + SA_LO + off, al[0], al[1], al[2], al[3]);
                    #pragma unroll
                    for (int nt = 0; nt < 4; nt++)
                        mma16816(acc[mt][nt][0], acc[mt][nt][1], acc[mt][nt][2], acc[mt][nt][3],
                                 al[0], al[1], al[2], al[3],
                                 bh[nt][0], bh[nt][1]);
                }
            }
        }

        __syncthreads();   // all warps done reading this stage
        if (k + 2 < NCHUNK) fill_stage(stage, m0, n0, (k + 2) * BK);
        cp_commit();       // empty groups keep the count symmetric
    }

    // ---------------- epilogue: fused elu, float2 stores ----------------
    const int gp  = lane >> 2;          // group id 0..7 (row)
    const int tg2 = (lane & 3) * 2;     // col pair
    #pragma unroll
    for (int mt = 0; mt < 4; mt++) {
        int mrow = m0 + warp_m * 64 + mt * 16 + gp;
        #pragma unroll
        for (int nt = 0; nt < 4; nt++) {
            int ncol = n0 + warp_n * 32 + nt * 8 + tg2;
            float2 v0, v1;
            v0.x = elu_f(acc[mt][nt][0]);
            v0.y = elu_f(acc[mt][nt][1]);
            v1.x = elu_f(acc[mt][nt][2]);
            v1.y = elu_f(acc[mt][nt][3]);
            *reinterpret_cast<float2*>(C + (size_t)mrow * GN + ncol) = v0;
            *reinterpret_cast<float2*>(C + (size_t)(mrow + 8) * GN + ncol) = v1;
        }
    }
}

// ---------------- launch ----------------
extern "C" void kernel_launch(void* const* d_in, const int* in_sizes, int n_in,
                              void* d_out, int out_size) {
    const float* input = (const float*)d_in[0];   // [8192, 2048]
    const float* W     = (const float*)d_in[2];   // [2048, 2048]
    float*       out   = (float*)d_out;

    cudaFuncSetAttribute(gat_mma_kernel,
                         cudaFuncAttributeMaxDynamicSharedMemorySize, SMEM_TOTAL);

    conv_a_kernel<<<(GM * (size_t)GK) / (256 * 4), 256>>>((const float4*)input);
    conv_bt_kernel<<<dim3(GN / 32, GK / 32), dim3(32, 8)>>>(W);
    gat_mma_kernel<<<dim3(GN / BN, GM / BM), NTHREADS, SMEM_TOTAL>>>(out);
}

// round 4
// speedup vs baseline: 2.7719x; 1.0166x over previous
#include <cuda_runtime.h>
#include <cuda_bf16.h>
#include <cstdint>

// out = elu(input @ W)  [reference's softmax(eye-mask) == Identity exactly]
// fp32 GEMM M=8192 N=2048 K=2048 via bf16 3-term split on mma.sync.m16n8k16:
//   A@B = Ahi@Bhi + Ahi@Blo + Alo@Bhi    (lo*lo ~2^-18, dropped)
// Pre-pass: A -> (Ahi,Alo) bf16 [M,K]; W -> transposed (Bhi,Blo) bf16 [N,K].
// Main: 128x256 CTA tile, BK=64, 16 warps (warp tile 64x32), 2-stage cp.async.
// R3: ILP restructure — B frags up front, A frag double-buffer (prefetch mt+1),
//     swizzle math hoisted to per-lane bases (addr = base + (kb ^ xmask)).

#define GM 8192
#define GN 2048
#define GK 2048

#define BM 128
#define BN 256
#define BK 64
#define NTHREADS 512
#define NCHUNK (GK / BK)   // 32

// ---------------- scratch (bf16 split operands) ----------------
__device__ __nv_bfloat16 g_Ahi[(size_t)GM * GK];
__device__ __nv_bfloat16 g_Alo[(size_t)GM * GK];
__device__ __nv_bfloat16 g_Bhi[(size_t)GN * GK];   // W^T, K-major rows
__device__ __nv_bfloat16 g_Blo[(size_t)GN * GK];

// ---------------- smem stage layout ----------------
#define SA_HI 0
#define SA_LO 16384
#define SB_HI 32768
#define SB_LO 65536
#define STAGE_BYTES 98304
#define SMEM_TOTAL (2 * STAGE_BYTES)   // 196608

#define SWZ(o) ((o) ^ (((o) >> 3) & 0x70))

__device__ __forceinline__ uint32_t smem_u32(const void* p) {
    uint32_t a;
    asm("{ .reg .u64 t; cvta.to.shared.u64 t, %1; cvt.u32.u64 %0, t; }" : "=r"(a) : "l"(p));
    return a;
}
__device__ __forceinline__ void cp16(uint32_t dst, const void* src) {
    asm volatile("cp.async.cg.shared.global [%0], [%1], 16;" :: "r"(dst), "l"(src));
}
__device__ __forceinline__ void cp_commit() {
    asm volatile("cp.async.commit_group;" ::: "memory");
}
__device__ __forceinline__ void cp_wait1() {
    asm volatile("cp.async.wait_group 1;" ::: "memory");
}
__device__ __forceinline__ void ldsm4(uint32_t addr, uint32_t& r0, uint32_t& r1,
                                      uint32_t& r2, uint32_t& r3) {
    asm volatile("ldmatrix.sync.aligned.m8n8.x4.shared.b16 {%0,%1,%2,%3}, [%4];"
                 : "=r"(r0), "=r"(r1), "=r"(r2), "=r"(r3) : "r"(addr));
}
__device__ __forceinline__ void mma16816(float& d0, float& d1, float& d2, float& d3,
                                         uint32_t a0, uint32_t a1, uint32_t a2, uint32_t a3,
                                         uint32_t b0, uint32_t b1) {
    asm volatile(
        "mma.sync.aligned.m16n8k16.row.col.f32.bf16.bf16.f32 "
        "{%0,%1,%2,%3}, {%4,%5,%6,%7}, {%8,%9}, {%0,%1,%2,%3};"
        : "+f"(d0), "+f"(d1), "+f"(d2), "+f"(d3)
        : "r"(a0), "r"(a1), "r"(a2), "r"(a3), "r"(b0), "r"(b1));
}
__device__ __forceinline__ float elu_f(float x) { return x > 0.0f ? x : expm1f(x); }

// ---------------- conversion kernels ----------------
__global__ __launch_bounds__(256) void conv_a_kernel(const float4* __restrict__ A) {
    size_t i = (size_t)blockIdx.x * 256 + threadIdx.x;
    float4 v = A[i];
    __nv_bfloat16 h0 = __float2bfloat16(v.x), h1 = __float2bfloat16(v.y);
    __nv_bfloat16 h2 = __float2bfloat16(v.z), h3 = __float2bfloat16(v.w);
    __nv_bfloat16 l0 = __float2bfloat16(v.x - __bfloat162float(h0));
    __nv_bfloat16 l1 = __float2bfloat16(v.y - __bfloat162float(h1));
    __nv_bfloat16 l2 = __float2bfloat16(v.z - __bfloat162float(h2));
    __nv_bfloat16 l3 = __float2bfloat16(v.w - __bfloat162float(h3));
    __nv_bfloat162* ph = reinterpret_cast<__nv_bfloat162*>(g_Ahi + i * 4);
    __nv_bfloat162* pl = reinterpret_cast<__nv_bfloat162*>(g_Alo + i * 4);
    ph[0] = __nv_bfloat162(h0, h1);
    ph[1] = __nv_bfloat162(h2, h3);
    pl[0] = __nv_bfloat162(l0, l1);
    pl[1] = __nv_bfloat162(l2, l3);
}

__global__ __launch_bounds__(256) void conv_bt_kernel(const float* __restrict__ B) {
    __shared__ float tile[32][33];
    int n0 = blockIdx.x * 32, k0 = blockIdx.y * 32;
    int tx = threadIdx.x, ty = threadIdx.y;   // block (32,8)
    #pragma unroll
    for (int j = 0; j < 32; j += 8)
        tile[ty + j][tx] = B[(size_t)(k0 + ty + j) * GN + n0 + tx];
    __syncthreads();
    #pragma unroll
    for (int j = 0; j < 32; j += 8) {
        float x = tile[tx][ty + j];
        __nv_bfloat16 h = __float2bfloat16(x);
        __nv_bfloat16 l = __float2bfloat16(x - __bfloat162float(h));
        size_t o = (size_t)(n0 + ty + j) * GK + k0 + tx;
        g_Bhi[o] = h;
        g_Blo[o] = l;
    }
}

// ---------------- stage fill ----------------
__device__ __forceinline__ void fill_stage(uint32_t sbase, int m0, int n0, int k0) {
    const int tid = threadIdx.x;
    const char* Ah = (const char*)g_Ahi;
    const char* Al = (const char*)g_Alo;
    const char* Bh = (const char*)g_Bhi;
    const char* Bl = (const char*)g_Blo;
    #pragma unroll
    for (int i = tid; i < 1024; i += NTHREADS) {
        int r = i >> 3, c = i & 7;
        uint32_t off = SWZ((uint32_t)(r * 128 + c * 16));
        size_t go = ((size_t)(m0 + r) * GK + k0) * 2 + c * 16;
        cp16(sbase + SA_HI + off, Ah + go);
        cp16(sbase + SA_LO + off, Al + go);
    }
    #pragma unroll
    for (int i = tid; i < 2048; i += NTHREADS) {
        int r = i >> 3, c = i & 7;
        uint32_t off = SWZ((uint32_t)(r * 128 + c * 16));
        size_t go = ((size_t)(n0 + r) * GK + k0) * 2 + c * 16;
        cp16(sbase + SB_HI + off, Bh + go);
        cp16(sbase + SB_LO + off, Bl + go);
    }
}

// ---------------- main GEMM kernel ----------------
__global__ __launch_bounds__(NTHREADS, 1)
void gat_mma_kernel(float* __restrict__ C) {
    extern __shared__ char smem[];
    uint32_t sb = smem_u32(smem);
    const int tid  = threadIdx.x;
    const int wid  = tid >> 5;
    const int lane = tid & 31;
    const int m0 = blockIdx.y * BM;
    const int n0 = blockIdx.x * BN;
    const int warp_m = wid & 1;    // 2 M-tiles of 64
    const int warp_n = wid >> 1;   // 8 N-tiles of 32

    float acc[4][4][4];
    #pragma unroll
    for (int i = 0; i < 4; i++)
        #pragma unroll
        for (int j = 0; j < 4; j++)
            #pragma unroll
            for (int t = 0; t < 4; t++) acc[i][j][t] = 0.0f;

    // ---- per-lane swizzled address bases ----
    // SWZ(row*128 + c) == row*128 + (c ^ ((row&7)<<4))  for c < 128
    const int a_row_l = lane & 15;
    const uint32_t a_kb = (uint32_t)((lane >> 4) << 4);   // 0 or 16
    const int b_j = lane >> 3;
    const int b_row_l = (lane & 7) + ((b_j >> 1) << 3);
    const uint32_t b_kb = (uint32_t)((b_j & 1) << 4);

    uint32_t baseA[4], xA[4];
    #pragma unroll
    for (int mt = 0; mt < 4; mt++) {
        int row = warp_m * 64 + mt * 16 + a_row_l;
        baseA[mt] = (uint32_t)(row << 7);
        xA[mt]    = (uint32_t)((row & 7) << 4);
    }
    uint32_t baseB[2], xB[2];
    #pragma unroll
    for (int np = 0; np < 2; np++) {
        int row = warp_n * 32 + np * 16 + b_row_l;
        baseB[np] = (uint32_t)(row << 7);
        xB[np]    = (uint32_t)((row & 7) << 4);
    }

    // prologue
    fill_stage(sb, m0, n0, 0);
    cp_commit();
    fill_stage(sb + STAGE_BYTES, m0, n0, BK);
    cp_commit();

    for (int k = 0; k < NCHUNK; k++) {
        uint32_t stage = sb + (uint32_t)(k & 1) * STAGE_BYTES;
        cp_wait1();
        __syncthreads();

        #pragma unroll
        for (int ks = 0; ks < 4; ks++) {
            const uint32_t kb = (uint32_t)(ks * 32);

            // ---- all B fragments first (hi then lo) ----
            uint32_t bh[4][2], bl[4][2];
            #pragma unroll
            for (int np = 0; np < 2; np++) {
                uint32_t ad = stage + SB_HI + baseB[np] + ((kb + b_kb) ^ xB[np]);
                uint32_t r0, r1, r2, r3;
                ldsm4(ad, r0, r1, r2, r3);
                bh[np * 2 + 0][0] = r0; bh[np * 2 + 0][1] = r1;
                bh[np * 2 + 1][0] = r2; bh[np * 2 + 1][1] = r3;
                ldsm4(ad + (SB_LO - SB_HI), r0, r1, r2, r3);
                bl[np * 2 + 0][0] = r0; bl[np * 2 + 0][1] = r1;
                bl[np * 2 + 1][0] = r2; bl[np * 2 + 1][1] = r3;
            }

            // ---- A fragments: double-buffered prefetch over mt ----
            uint32_t ah[2][4], al[2][4];
            {
                uint32_t ad = stage + SA_HI + baseA[0] + ((kb + a_kb) ^ xA[0]);
                ldsm4(ad, ah[0][0], ah[0][1], ah[0][2], ah[0][3]);
                ldsm4(ad + (SA_LO - SA_HI), al[0][0], al[0][1], al[0][2], al[0][3]);
            }
            #pragma unroll
            for (int mt = 0; mt < 4; mt++) {
                const int cb = mt & 1;
                if (mt < 3) {
                    const int nb = (mt + 1) & 1;
                    uint32_t ad = stage + SA_HI + baseA[mt + 1] + ((kb + a_kb) ^ xA[mt + 1]);
                    ldsm4(ad, ah[nb][0], ah[nb][1], ah[nb][2], ah[nb][3]);
                    ldsm4(ad + (SA_LO - SA_HI), al[nb][0], al[nb][1], al[nb][2], al[nb][3]);
                }
                #pragma unroll
                for (int nt = 0; nt < 4; nt++)
                    mma16816(acc[mt][nt][0], acc[mt][nt][1], acc[mt][nt][2], acc[mt][nt][3],
                             ah[cb][0], ah[cb][1], ah[cb][2], ah[cb][3],
                             bh[nt][0], bh[nt][1]);
                #pragma unroll
                for (int nt = 0; nt < 4; nt++)
                    mma16816(acc[mt][nt][0], acc[mt][nt][1], acc[mt][nt][2], acc[mt][nt][3],
                             ah[cb][0], ah[cb][1], ah[cb][2], ah[cb][3],
                             bl[nt][0], bl[nt][1]);
                #pragma unroll
                for (int nt = 0; nt < 4; nt++)
                    mma16816(acc[mt][nt][0], acc[mt][nt][1], acc[mt][nt][2], acc[mt][nt][3],
                             al[cb][0], al[cb][1], al[cb][2], al[cb][3],
                             bh[nt][0], bh[nt][1]);
            }
        }

        __syncthreads();   // all warps done reading this stage
        if (k + 2 < NCHUNK) fill_stage(stage, m0, n0, (k + 2) * BK);
        cp_commit();       // empty groups keep the count symmetric
    }

    // ---------------- epilogue: fused elu, float2 stores ----------------
    const int gp  = lane >> 2;
    const int tg2 = (lane & 3) * 2;
    #pragma unroll
    for (int mt = 0; mt < 4; mt++) {
        int mrow = m0 + warp_m * 64 + mt * 16 + gp;
        #pragma unroll
        for (int nt = 0; nt < 4; nt++) {
            int ncol = n0 + warp_n * 32 + nt * 8 + tg2;
            float2 v0, v1;
            v0.x = elu_f(acc[mt][nt][0]);
            v0.y = elu_f(acc[mt][nt][1]);
            v1.x = elu_f(acc[mt][nt][2]);
            v1.y = elu_f(acc[mt][nt][3]);
            *reinterpret_cast<float2*>(C + (size_t)mrow * GN + ncol) = v0;
            *reinterpret_cast<float2*>(C + (size_t)(mrow + 8) * GN + ncol) = v1;
        }
    }
}

// ---------------- launch ----------------
extern "C" void kernel_launch(void* const* d_in, const int* in_sizes, int n_in,
                              void* d_out, int out_size) {
    const float* input = (const float*)d_in[0];   // [8192, 2048]
    const float* W     = (const float*)d_in[2];   // [2048, 2048]
    float*       out   = (float*)d_out;

    cudaFuncSetAttribute(gat_mma_kernel,
                         cudaFuncAttributeMaxDynamicSharedMemorySize, SMEM_TOTAL);

    conv_a_kernel<<<(GM * (size_t)GK) / (256 * 4), 256>>>((const float4*)input);
    conv_bt_kernel<<<dim3(GN / 32, GK / 32), dim3(32, 8)>>>(W);
    gat_mma_kernel<<<dim3(GN / BN, GM / BM), NTHREADS, SMEM_TOTAL>>>(out);
}

// round 5
// speedup vs baseline: 3.9468x; 1.4239x over previous
#include <cuda_runtime.h>
#include <cuda_fp16.h>
#include <cstdint>

// out = elu(input @ W)  [reference's softmax(eye-mask) == Identity exactly]
// fp32 GEMM M=8192 N=2048 K=2048. The legacy mma.sync pipe is the throughput
// ceiling (R3 post-mortem), so minimize MMA instruction count:
// 2-term fp16 split (A double-fp16, B single fp16):
//   C = Ah@Bh + Al@Bh = (Ah+Al)@Bh ~= A@Bh ;  error ~2^-12 (~1.5e-4 << 1e-3)
// Pre-pass: A -> (Ah,Al) fp16 [M,K]; W -> transposed Bh fp16 [N,K].
// Main: 128x256 CTA tile, BK=64, 16 warps (warp tile 64x32), 3-stage cp.async.

#define GM 8192
#define GN 2048
#define GK 2048

#define BM 128
#define BN 256
#define BK 64
#define NTHREADS 512
#define NCHUNK (GK / BK)   // 32

// ---------------- scratch (fp16 operands) ----------------
__device__ __half g_Ahi[(size_t)GM * GK];
__device__ __half g_Alo[(size_t)GM * GK];
__device__ __half g_Bhi[(size_t)GN * GK];   // W^T, K-major rows

// ---------------- smem stage layout ----------------
// per stage: Ahi 16K | Alo 16K | Bhi 32K   (rows of 128B, SW128)
#define SA_HI 0
#define SA_LO 16384
#define SB_HI 32768
#define STAGE_BYTES 65536
#define NSTAGE 3
#define SMEM_TOTAL (NSTAGE * STAGE_BYTES)   // 196608

#define SWZ(o) ((o) ^ (((o) >> 3) & 0x70))

__device__ __forceinline__ uint32_t smem_u32(const void* p) {
    uint32_t a;
    asm("{ .reg .u64 t; cvta.to.shared.u64 t, %1; cvt.u32.u64 %0, t; }" : "=r"(a) : "l"(p));
    return a;
}
__device__ __forceinline__ void cp16(uint32_t dst, const void* src) {
    asm volatile("cp.async.cg.shared.global [%0], [%1], 16;" :: "r"(dst), "l"(src));
}
__device__ __forceinline__ void cp_commit() {
    asm volatile("cp.async.commit_group;" ::: "memory");
}
__device__ __forceinline__ void cp_wait2() {
    asm volatile("cp.async.wait_group 2;" ::: "memory");
}
__device__ __forceinline__ void ldsm4(uint32_t addr, uint32_t& r0, uint32_t& r1,
                                      uint32_t& r2, uint32_t& r3) {
    asm volatile("ldmatrix.sync.aligned.m8n8.x4.shared.b16 {%0,%1,%2,%3}, [%4];"
                 : "=r"(r0), "=r"(r1), "=r"(r2), "=r"(r3) : "r"(addr));
}
__device__ __forceinline__ void mma16816(float& d0, float& d1, float& d2, float& d3,
                                         uint32_t a0, uint32_t a1, uint32_t a2, uint32_t a3,
                                         uint32_t b0, uint32_t b1) {
    asm volatile(
        "mma.sync.aligned.m16n8k16.row.col.f32.f16.f16.f32 "
        "{%0,%1,%2,%3}, {%4,%5,%6,%7}, {%8,%9}, {%0,%1,%2,%3};"
        : "+f"(d0), "+f"(d1), "+f"(d2), "+f"(d3)
        : "r"(a0), "r"(a1), "r"(a2), "r"(a3), "r"(b0), "r"(b1));
}
__device__ __forceinline__ float elu_f(float x) { return x > 0.0f ? x : expm1f(x); }

// ---------------- conversion kernels ----------------
__global__ __launch_bounds__(256) void conv_a_kernel(const float4* __restrict__ A) {
    size_t i = (size_t)blockIdx.x * 256 + threadIdx.x;
    float4 v = A[i];
    __half h0 = __float2half(v.x), h1 = __float2half(v.y);
    __half h2 = __float2half(v.z), h3 = __float2half(v.w);
    __half l0 = __float2half(v.x - __half2float(h0));
    __half l1 = __float2half(v.y - __half2float(h1));
    __half l2 = __float2half(v.z - __half2float(h2));
    __half l3 = __float2half(v.w - __half2float(h3));
    __half2* ph = reinterpret_cast<__half2*>(g_Ahi + i * 4);
    __half2* pl = reinterpret_cast<__half2*>(g_Alo + i * 4);
    ph[0] = __half2(h0, h1);
    ph[1] = __half2(h2, h3);
    pl[0] = __half2(l0, l1);
    pl[1] = __half2(l2, l3);
}

__global__ __launch_bounds__(256) void conv_bt_kernel(const float* __restrict__ B) {
    __shared__ float tile[32][33];
    int n0 = blockIdx.x * 32, k0 = blockIdx.y * 32;
    int tx = threadIdx.x, ty = threadIdx.y;   // block (32,8)
    #pragma unroll
    for (int j = 0; j < 32; j += 8)
        tile[ty + j][tx] = B[(size_t)(k0 + ty + j) * GN + n0 + tx];
    __syncthreads();
    #pragma unroll
    for (int j = 0; j < 32; j += 8) {
        float x = tile[tx][ty + j];
        g_Bhi[(size_t)(n0 + ty + j) * GK + k0 + tx] = __float2half(x);
    }
}

// ---------------- stage fill ----------------
__device__ __forceinline__ void fill_stage(uint32_t sbase, int m0, int n0, int k0) {
    const int tid = threadIdx.x;
    const char* Ah = (const char*)g_Ahi;
    const char* Al = (const char*)g_Alo;
    const char* Bh = (const char*)g_Bhi;
    // A tiles: 128 rows x 128B, hi+lo
    #pragma unroll
    for (int i = tid; i < 1024; i += NTHREADS) {
        int r = i >> 3, c = i & 7;
        uint32_t off = SWZ((uint32_t)(r * 128 + c * 16));
        size_t go = ((size_t)(m0 + r) * GK + k0) * 2 + c * 16;
        cp16(sbase + SA_HI + off, Ah + go);
        cp16(sbase + SA_LO + off, Al + go);
    }
    // B tile: 256 rows x 128B
    #pragma unroll
    for (int i = tid; i < 2048; i += NTHREADS) {
        int r = i >> 3, c = i & 7;
        uint32_t off = SWZ((uint32_t)(r * 128 + c * 16));
        size_t go = ((size_t)(n0 + r) * GK + k0) * 2 + c * 16;
        cp16(sbase + SB_HI + off, Bh + go);
    }
}

// ---------------- main GEMM kernel ----------------
__global__ __launch_bounds__(NTHREADS, 1)
void gat_mma_kernel(float* __restrict__ C) {
    extern __shared__ char smem[];
    uint32_t sb = smem_u32(smem);
    const int tid  = threadIdx.x;
    const int wid  = tid >> 5;
    const int lane = tid & 31;
    const int m0 = blockIdx.y * BM;
    const int n0 = blockIdx.x * BN;
    const int warp_m = wid & 1;    // 2 M-tiles of 64
    const int warp_n = wid >> 1;   // 8 N-tiles of 32

    float acc[4][4][4];
    #pragma unroll
    for (int i = 0; i < 4; i++)
        #pragma unroll
        for (int j = 0; j < 4; j++)
            #pragma unroll
            for (int t = 0; t < 4; t++) acc[i][j][t] = 0.0f;

    // per-lane swizzled address bases:
    // SWZ(row*128 + c) == row*128 + (c ^ ((row&7)<<4))  for c < 128
    const int a_row_l = lane & 15;
    const uint32_t a_kb = (uint32_t)((lane >> 4) << 4);
    const int b_j = lane >> 3;
    const int b_row_l = (lane & 7) + ((b_j >> 1) << 3);
    const uint32_t b_kb = (uint32_t)((b_j & 1) << 4);

    uint32_t baseA[4], xA[4];
    #pragma unroll
    for (int mt = 0; mt < 4; mt++) {
        int row = warp_m * 64 + mt * 16 + a_row_l;
        baseA[mt] = (uint32_t)(row << 7);
        xA[mt]    = (uint32_t)((row & 7) << 4);
    }
    uint32_t baseB[2], xB[2];
    #pragma unroll
    for (int np = 0; np < 2; np++) {
        int row = warp_n * 32 + np * 16 + b_row_l;
        baseB[np] = (uint32_t)(row << 7);
        xB[np]    = (uint32_t)((row & 7) << 4);
    }

    // prologue: fill 3 stages
    fill_stage(sb, m0, n0, 0);
    cp_commit();
    fill_stage(sb + STAGE_BYTES, m0, n0, BK);
    cp_commit();
    fill_stage(sb + 2 * STAGE_BYTES, m0, n0, 2 * BK);
    cp_commit();

    int stage_idx = 0;
    for (int k = 0; k < NCHUNK; k++) {
        uint32_t stage = sb + (uint32_t)stage_idx * STAGE_BYTES;
        cp_wait2();   // chunk k resident
        __syncthreads();

        #pragma unroll
        for (int ks = 0; ks < 4; ks++) {
            const uint32_t kb = (uint32_t)(ks * 32);

            // B fragments (hi only): 2 ldsm cover 4 n-tiles
            uint32_t bh[4][2];
            #pragma unroll
            for (int np = 0; np < 2; np++) {
                uint32_t ad = stage + SB_HI + baseB[np] + ((kb + b_kb) ^ xB[np]);
                uint32_t r0, r1, r2, r3;
                ldsm4(ad, r0, r1, r2, r3);
                bh[np * 2 + 0][0] = r0; bh[np * 2 + 0][1] = r1;
                bh[np * 2 + 1][0] = r2; bh[np * 2 + 1][1] = r3;
            }

            // A fragments double-buffered over mt; 8 MMAs per mt
            uint32_t ah[2][4], al[2][4];
            {
                uint32_t ad = stage + SA_HI + baseA[0] + ((kb + a_kb) ^ xA[0]);
                ldsm4(ad, ah[0][0], ah[0][1], ah[0][2], ah[0][3]);
                ldsm4(ad + (SA_LO - SA_HI), al[0][0], al[0][1], al[0][2], al[0][3]);
            }
            #pragma unroll
            for (int mt = 0; mt < 4; mt++) {
                const int cb = mt & 1;
                if (mt < 3) {
                    const int nb = (mt + 1) & 1;
                    uint32_t ad = stage + SA_HI + baseA[mt + 1] + ((kb + a_kb) ^ xA[mt + 1]);
                    ldsm4(ad, ah[nb][0], ah[nb][1], ah[nb][2], ah[nb][3]);
                    ldsm4(ad + (SA_LO - SA_HI), al[nb][0], al[nb][1], al[nb][2], al[nb][3]);
                }
                #pragma unroll
                for (int nt = 0; nt < 4; nt++)
                    mma16816(acc[mt][nt][0], acc[mt][nt][1], acc[mt][nt][2], acc[mt][nt][3],
                             ah[cb][0], ah[cb][1], ah[cb][2], ah[cb][3],
                             bh[nt][0], bh[nt][1]);
                #pragma unroll
                for (int nt = 0; nt < 4; nt++)
                    mma16816(acc[mt][nt][0], acc[mt][nt][1], acc[mt][nt][2], acc[mt][nt][3],
                             al[cb][0], al[cb][1], al[cb][2], al[cb][3],
                             bh[nt][0], bh[nt][1]);
            }
        }

        __syncthreads();   // all warps done reading this stage
        if (k + NSTAGE < NCHUNK) fill_stage(stage, m0, n0, (k + NSTAGE) * BK);
        cp_commit();       // one group per iter keeps wait_group accounting
        stage_idx = (stage_idx == NSTAGE - 1) ? 0 : stage_idx + 1;
    }

    // ---------------- epilogue: fused elu, float2 stores ----------------
    const int gp  = lane >> 2;
    const int tg2 = (lane & 3) * 2;
    #pragma unroll
    for (int mt = 0; mt < 4; mt++) {
        int mrow = m0 + warp_m * 64 + mt * 16 + gp;
        #pragma unroll
        for (int nt = 0; nt < 4; nt++) {
            int ncol = n0 + warp_n * 32 + nt * 8 + tg2;
            float2 v0, v1;
            v0.x = elu_f(acc[mt][nt][0]);
            v0.y = elu_f(acc[mt][nt][1]);
            v1.x = elu_f(acc[mt][nt][2]);
            v1.y = elu_f(acc[mt][nt][3]);
            *reinterpret_cast<float2*>(C + (size_t)mrow * GN + ncol) = v0;
            *reinterpret_cast<float2*>(C + (size_t)(mrow + 8) * GN + ncol) = v1;
        }
    }
}

// ---------------- launch ----------------
extern "C" void kernel_launch(void* const* d_in, const int* in_sizes, int n_in,
                              void* d_out, int out_size) {
    const float* input = (const float*)d_in[0];   // [8192, 2048]
    const float* W     = (const float*)d_in[2];   // [2048, 2048]
    float*       out   = (float*)d_out;

    cudaFuncSetAttribute(gat_mma_kernel,
                         cudaFuncAttributeMaxDynamicSharedMemorySize, SMEM_TOTAL);

    conv_a_kernel<<<(GM * (size_t)GK) / (256 * 4), 256>>>((const float4*)input);
    conv_bt_kernel<<<dim3(GN / 32, GK / 32), dim3(32, 8)>>>(W);
    gat_mma_kernel<<<dim3(GN / BN, GM / BM), NTHREADS, SMEM_TOTAL>>>(out);
}

// round 6
// speedup vs baseline: 6.1268x; 1.5523x over previous
#include <cuda_runtime.h>
#include <cuda_fp16.h>
#include <cstdint>

// out = elu(input @ W)  [reference's softmax(eye-mask) == Identity exactly]
// fp32 GEMM M=8192 N=2048 K=2048 on mma.sync.m16n8k16 (HMMA issue-bound:
// measured time scales linearly with MMA count — 3 terms 549us, 2 terms 379us).
// R5: single fp16 term. C ~= Ah@Bh, both operands RN-rounded fp16.
// Measured B-only error was 2.1e-4; A adds ~same independently -> ~3e-4 < 1e-3.
// Main: 128x256 CTA tile, BK=64, 16 warps (warp tile 64x32), 3-stage cp.async.

#define GM 8192
#define GN 2048
#define GK 2048

#define BM 128
#define BN 256
#define BK 64
#define NTHREADS 512
#define NCHUNK (GK / BK)   // 32

// ---------------- scratch (fp16 operands) ----------------
__device__ __half g_Ah[(size_t)GM * GK];
__device__ __half g_Bh[(size_t)GN * GK];   // W^T, K-major rows

// ---------------- smem stage layout ----------------
// per stage: Ah 16K | Bh 32K   (rows of 128B, SW128)
#define SA 0
#define SB 16384
#define STAGE_BYTES 49152
#define NSTAGE 3
#define SMEM_TOTAL (NSTAGE * STAGE_BYTES)   // 147456

#define SWZ(o) ((o) ^ (((o) >> 3) & 0x70))

__device__ __forceinline__ uint32_t smem_u32(const void* p) {
    uint32_t a;
    asm("{ .reg .u64 t; cvta.to.shared.u64 t, %1; cvt.u32.u64 %0, t; }" : "=r"(a) : "l"(p));
    return a;
}
__device__ __forceinline__ void cp16(uint32_t dst, const void* src) {
    asm volatile("cp.async.cg.shared.global [%0], [%1], 16;" :: "r"(dst), "l"(src));
}
__device__ __forceinline__ void cp_commit() {
    asm volatile("cp.async.commit_group;" ::: "memory");
}
__device__ __forceinline__ void cp_wait2() {
    asm volatile("cp.async.wait_group 2;" ::: "memory");
}
__device__ __forceinline__ void ldsm4(uint32_t addr, uint32_t& r0, uint32_t& r1,
                                      uint32_t& r2, uint32_t& r3) {
    asm volatile("ldmatrix.sync.aligned.m8n8.x4.shared.b16 {%0,%1,%2,%3}, [%4];"
                 : "=r"(r0), "=r"(r1), "=r"(r2), "=r"(r3) : "r"(addr));
}
__device__ __forceinline__ void mma16816(float& d0, float& d1, float& d2, float& d3,
                                         uint32_t a0, uint32_t a1, uint32_t a2, uint32_t a3,
                                         uint32_t b0, uint32_t b1) {
    asm volatile(
        "mma.sync.aligned.m16n8k16.row.col.f32.f16.f16.f32 "
        "{%0,%1,%2,%3}, {%4,%5,%6,%7}, {%8,%9}, {%0,%1,%2,%3};"
        : "+f"(d0), "+f"(d1), "+f"(d2), "+f"(d3)
        : "r"(a0), "r"(a1), "r"(a2), "r"(a3), "r"(b0), "r"(b1));
}
__device__ __forceinline__ float elu_f(float x) { return x > 0.0f ? x : expm1f(x); }

// ---------------- conversion kernels ----------------
__global__ __launch_bounds__(256) void conv_a_kernel(const float4* __restrict__ A) {
    size_t i = (size_t)blockIdx.x * 256 + threadIdx.x;
    float4 v = A[i];
    __half2* ph = reinterpret_cast<__half2*>(g_Ah + i * 4);
    ph[0] = __half2(__float2half(v.x), __float2half(v.y));
    ph[1] = __half2(__float2half(v.z), __float2half(v.w));
}

__global__ __launch_bounds__(256) void conv_bt_kernel(const float* __restrict__ B) {
    __shared__ float tile[32][33];
    int n0 = blockIdx.x * 32, k0 = blockIdx.y * 32;
    int tx = threadIdx.x, ty = threadIdx.y;   // block (32,8)
    #pragma unroll
    for (int j = 0; j < 32; j += 8)
        tile[ty + j][tx] = B[(size_t)(k0 + ty + j) * GN + n0 + tx];
    __syncthreads();
    #pragma unroll
    for (int j = 0; j < 32; j += 8) {
        float x = tile[tx][ty + j];
        g_Bh[(size_t)(n0 + ty + j) * GK + k0 + tx] = __float2half(x);
    }
}

// ---------------- stage fill ----------------
__device__ __forceinline__ void fill_stage(uint32_t sbase, int m0, int n0, int k0) {
    const int tid = threadIdx.x;
    const char* Ah = (const char*)g_Ah;
    const char* Bh = (const char*)g_Bh;
    // A tile: 128 rows x 128B
    #pragma unroll
    for (int i = tid; i < 1024; i += NTHREADS) {
        int r = i >> 3, c = i & 7;
        uint32_t off = SWZ((uint32_t)(r * 128 + c * 16));
        size_t go = ((size_t)(m0 + r) * GK + k0) * 2 + c * 16;
        cp16(sbase + SA + off, Ah + go);
    }
    // B tile: 256 rows x 128B
    #pragma unroll
    for (int i = tid; i < 2048; i += NTHREADS) {
        int r = i >> 3, c = i & 7;
        uint32_t off = SWZ((uint32_t)(r * 128 + c * 16));
        size_t go = ((size_t)(n0 + r) * GK + k0) * 2 + c * 16;
        cp16(sbase + SB + off, Bh + go);
    }
}

// ---------------- main GEMM kernel ----------------
__global__ __launch_bounds__(NTHREADS, 1)
void gat_mma_kernel(float* __restrict__ C) {
    extern __shared__ char smem[];
    uint32_t sb = smem_u32(smem);
    const int tid  = threadIdx.x;
    const int wid  = tid >> 5;
    const int lane = tid & 31;
    const int m0 = blockIdx.y * BM;
    const int n0 = blockIdx.x * BN;
    const int warp_m = wid & 1;    // 2 M-tiles of 64
    const int warp_n = wid >> 1;   // 8 N-tiles of 32

    float acc[4][4][4];
    #pragma unroll
    for (int i = 0; i < 4; i++)
        #pragma unroll
        for (int j = 0; j < 4; j++)
            #pragma unroll
            for (int t = 0; t < 4; t++) acc[i][j][t] = 0.0f;

    // per-lane swizzled address bases:
    // SWZ(row*128 + c) == row*128 + (c ^ ((row&7)<<4))  for c < 128
    const int a_row_l = lane & 15;
    const uint32_t a_kb = (uint32_t)((lane >> 4) << 4);
    const int b_j = lane >> 3;
    const int b_row_l = (lane & 7) + ((b_j >> 1) << 3);
    const uint32_t b_kb = (uint32_t)((b_j & 1) << 4);

    uint32_t baseA[4], xA[4];
    #pragma unroll
    for (int mt = 0; mt < 4; mt++) {
        int row = warp_m * 64 + mt * 16 + a_row_l;
        baseA[mt] = (uint32_t)(row << 7);
        xA[mt]    = (uint32_t)((row & 7) << 4);
    }
    uint32_t baseB[2], xB[2];
    #pragma unroll
    for (int np = 0; np < 2; np++) {
        int row = warp_n * 32 + np * 16 + b_row_l;
        baseB[np] = (uint32_t)(row << 7);
        xB[np]    = (uint32_t)((row & 7) << 4);
    }

    // prologue: fill 3 stages
    fill_stage(sb, m0, n0, 0);
    cp_commit();
    fill_stage(sb + STAGE_BYTES, m0, n0, BK);
    cp_commit();
    fill_stage(sb + 2 * STAGE_BYTES, m0, n0, 2 * BK);
    cp_commit();

    int stage_idx = 0;
    for (int k = 0; k < NCHUNK; k++) {
        uint32_t stage = sb + (uint32_t)stage_idx * STAGE_BYTES;
        cp_wait2();   // chunk k resident
        __syncthreads();

        #pragma unroll
        for (int ks = 0; ks < 4; ks++) {
            const uint32_t kb = (uint32_t)(ks * 32);

            // B fragments: 2 ldsm.x4 cover 4 n-tiles
            uint32_t bh[4][2];
            #pragma unroll
            for (int np = 0; np < 2; np++) {
                uint32_t ad = stage + SB + baseB[np] + ((kb + b_kb) ^ xB[np]);
                uint32_t r0, r1, r2, r3;
                ldsm4(ad, r0, r1, r2, r3);
                bh[np * 2 + 0][0] = r0; bh[np * 2 + 0][1] = r1;
                bh[np * 2 + 1][0] = r2; bh[np * 2 + 1][1] = r3;
            }

            // A fragments double-buffered over mt; 4 MMAs per mt
            uint32_t ah[2][4];
            {
                uint32_t ad = stage + SA + baseA[0] + ((kb + a_kb) ^ xA[0]);
                ldsm4(ad, ah[0][0], ah[0][1], ah[0][2], ah[0][3]);
            }
            #pragma unroll
            for (int mt = 0; mt < 4; mt++) {
                const int cb = mt & 1;
                if (mt < 3) {
                    const int nb = (mt + 1) & 1;
                    uint32_t ad = stage + SA + baseA[mt + 1] + ((kb + a_kb) ^ xA[mt + 1]);
                    ldsm4(ad, ah[nb][0], ah[nb][1], ah[nb][2], ah[nb][3]);
                }
                #pragma unroll
                for (int nt = 0; nt < 4; nt++)
                    mma16816(acc[mt][nt][0], acc[mt][nt][1], acc[mt][nt][2], acc[mt][nt][3],
                             ah[cb][0], ah[cb][1], ah[cb][2], ah[cb][3],
                             bh[nt][0], bh[nt][1]);
            }
        }

        __syncthreads();   // all warps done reading this stage
        if (k + NSTAGE < NCHUNK) fill_stage(stage, m0, n0, (k + NSTAGE) * BK);
        cp_commit();       // one group per iter keeps wait_group accounting
        stage_idx = (stage_idx == NSTAGE - 1) ? 0 : stage_idx + 1;
    }

    // ---------------- epilogue: fused elu, float2 stores ----------------
    const int gp  = lane >> 2;
    const int tg2 = (lane & 3) * 2;
    #pragma unroll
    for (int mt = 0; mt < 4; mt++) {
        int mrow = m0 + warp_m * 64 + mt * 16 + gp;
        #pragma unroll
        for (int nt = 0; nt < 4; nt++) {
            int ncol = n0 + warp_n * 32 + nt * 8 + tg2;
            float2 v0, v1;
            v0.x = elu_f(acc[mt][nt][0]);
            v0.y = elu_f(acc[mt][nt][1]);
            v1.x = elu_f(acc[mt][nt][2]);
            v1.y = elu_f(acc[mt][nt][3]);
            *reinterpret_cast<float2*>(C + (size_t)mrow * GN + ncol) = v0;
            *reinterpret_cast<float2*>(C + (size_t)(mrow + 8) * GN + ncol) = v1;
        }
    }
}

// ---------------- launch ----------------
extern "C" void kernel_launch(void* const* d_in, const int* in_sizes, int n_in,
                              void* d_out, int out_size) {
    const float* input = (const float*)d_in[0];   // [8192, 2048]
    const float* W     = (const float*)d_in[2];   // [2048, 2048]
    float*       out   = (float*)d_out;

    cudaFuncSetAttribute(gat_mma_kernel,
                         cudaFuncAttributeMaxDynamicSharedMemorySize, SMEM_TOTAL);

    conv_a_kernel<<<(GM * (size_t)GK) / (256 * 4), 256>>>((const float4*)input);
    conv_bt_kernel<<<dim3(GN / 32, GK / 32), dim3(32, 8)>>>(W);
    gat_mma_kernel<<<dim3(GN / BN, GM / BM), NTHREADS, SMEM_TOTAL>>>(out);
}